// round 3
// baseline (speedup 1.0000x reference)
#include <cuda_runtime.h>
#include <cuda_bf16.h>
#include <math.h>

// Problem constants (from reference): N=100000, E=1600000, D_IN=128, D_H=128, D_OUT=64
#define NN 100000
#define EE 1600000
#define KDIM 128

// -------- device-global scratch (allocations are forbidden) --------
__device__ float g_bufA[(size_t)NN * 128];   // GEMM output G (layer1: 128 wide, layer2: 64 wide)
__device__ float g_bufB[(size_t)NN * 128];   // post-aggregation activations (layer1)
__device__ int   g_cnt[NN];
__device__ int   g_rowptr[NN + 1];
__device__ int   g_wp[NN];
__device__ int   g_col[EE];
__device__ float g_dinv[NN];
__device__ int   g_bsum[512];
__device__ int   g_boff[512];

// ----------------- CSR build -----------------
__global__ void k_zero_cnt(int n) {
    int i = blockIdx.x * blockDim.x + threadIdx.x;
    if (i < n) g_cnt[i] = 0;
}

__global__ void k_count(const int* __restrict__ dst, int e) {
    int i = blockIdx.x * blockDim.x + threadIdx.x;
    if (i < e) atomicAdd(&g_cnt[dst[i]], 1);
}

__global__ void k_dinv(int n) {
    int i = blockIdx.x * blockDim.x + threadIdx.x;
    if (i < n) g_dinv[i] = rsqrtf((float)g_cnt[i] + 1.0f);  // + self loop
}

// block-wise exclusive scan, 512/block
__global__ void k_scan1(int n) {
    __shared__ int sh[512];
    int tid = threadIdx.x;
    int i = blockIdx.x * 512 + tid;
    int v = (i < n) ? g_cnt[i] : 0;
    sh[tid] = v;
    __syncthreads();
#pragma unroll
    for (int off = 1; off < 512; off <<= 1) {
        int t = (tid >= off) ? sh[tid - off] : 0;
        __syncthreads();
        sh[tid] += t;
        __syncthreads();
    }
    int incl = sh[tid];
    if (i < n) g_rowptr[i] = incl - v;  // exclusive
    if (tid == 511) g_bsum[blockIdx.x] = incl;
}

__global__ void k_scan2(int nb, int n) {
    // single thread: scan the (<=512) block sums
    int run = 0;
    for (int b = 0; b < nb; b++) {
        g_boff[b] = run;
        run += g_bsum[b];
    }
    g_rowptr[n] = run;
}

__global__ void k_scan3(int n) {
    int i = blockIdx.x * 512 + threadIdx.x;
    if (i < n) {
        int v = g_rowptr[i] + g_boff[blockIdx.x];
        g_rowptr[i] = v;
        g_wp[i] = v;
    }
}

__global__ void k_fill(const int* __restrict__ src, const int* __restrict__ dst, int e) {
    int i = blockIdx.x * blockDim.x + threadIdx.x;
    if (i < e) {
        int d = dst[i];
        int pos = atomicAdd(&g_wp[d], 1);
        g_col[pos] = src[i];
    }
}

// ----------------- GEMM with dinv row-scale epilogue -----------------
// G[r, :] = dinv[r] * (X[r, :] @ W)     (X: n x 128 row-major, W: 128 x NCOL row-major)
template <int NCOL>
__global__ void k_gemm_scale(const float* __restrict__ X, const float* __restrict__ W,
                             float* __restrict__ G, int n) {
    constexpr int K = KDIM;
    constexpr int MT = 64;                // rows per CTA
    constexpr int COLT = NCOL / 4;        // threads across columns (each does 4 cols)
    constexpr int ROWT = 256 / COLT;      // threads across rows
    constexpr int RPT = MT / ROWT;        // rows per thread
    constexpr int XP = 129;               // padded X pitch (bank spread)

    extern __shared__ float sh[];
    float* sW = sh;                  // K * NCOL
    float* sX = sh + K * NCOL;       // MT * XP

    const int tid = threadIdx.x;
    const int tx = tid % COLT;
    const int ty = tid / COLT;
    const int rowBase = blockIdx.x * MT;

    // load W (coalesced float4)
    const float4* W4 = (const float4*)W;
    float4* sW4 = (float4*)sW;
    for (int i = tid; i < K * NCOL / 4; i += 256) sW4[i] = W4[i];

    // load X tile (64 x 128) into padded smem
    for (int i = tid; i < MT * (K / 4); i += 256) {
        int r = i / (K / 4);
        int c4 = i % (K / 4);
        float4 v = make_float4(0.f, 0.f, 0.f, 0.f);
        int gr = rowBase + r;
        if (gr < n) v = ((const float4*)X)[(size_t)gr * (K / 4) + c4];
        float* p = &sX[r * XP + c4 * 4];
        p[0] = v.x; p[1] = v.y; p[2] = v.z; p[3] = v.w;
    }
    __syncthreads();

    float acc[RPT][4];
#pragma unroll
    for (int j = 0; j < RPT; j++) {
        acc[j][0] = 0.f; acc[j][1] = 0.f; acc[j][2] = 0.f; acc[j][3] = 0.f;
    }

#pragma unroll 4
    for (int k = 0; k < K; k++) {
        float4 b = ((const float4*)sW)[k * COLT + tx];
        float a[RPT];
#pragma unroll
        for (int j = 0; j < RPT; j++) a[j] = sX[(ty * RPT + j) * XP + k];
#pragma unroll
        for (int j = 0; j < RPT; j++) {
            acc[j][0] += a[j] * b.x;
            acc[j][1] += a[j] * b.y;
            acc[j][2] += a[j] * b.z;
            acc[j][3] += a[j] * b.w;
        }
    }

#pragma unroll
    for (int j = 0; j < RPT; j++) {
        int r = rowBase + ty * RPT + j;
        if (r < n) {
            float s = g_dinv[r];
            float4 o;
            o.x = s * acc[j][0]; o.y = s * acc[j][1];
            o.z = s * acc[j][2]; o.w = s * acc[j][3];
            ((float4*)G)[((size_t)r * NCOL + tx * 4) / 4] = o;
        }
    }
}

// ----------------- aggregation: one warp per destination node -----------------
// out[d] = act( dinv[d] * (sum_{s in N(d)} G[s] + G[d]) + bias )
// LAYER2=false: D=128, SELU.  LAYER2=true: D=64, log_softmax over row.
template <int D, bool LAYER2>
__global__ void k_agg(const float* __restrict__ G, const float* __restrict__ bias,
                      float* __restrict__ out, int n) {
    const int warp = (blockIdx.x * blockDim.x + threadIdx.x) >> 5;
    const int lane = threadIdx.x & 31;
    if (warp >= n) return;
    constexpr int VPL = D / 32;  // floats per lane (4 or 2)

    float acc[VPL];
    // self loop
    {
        const float* row = G + (size_t)warp * D;
        if (VPL == 4) {
            float4 v = ((const float4*)row)[lane];
            acc[0] = v.x; acc[1] = v.y; acc[2] = v.z; acc[3] = v.w;
        } else {
            float2 v = ((const float2*)row)[lane];
            acc[0] = v.x; acc[1] = v.y;
        }
    }

    int r = g_rowptr[warp];
    const int end = g_rowptr[warp + 1];

    // unroll-4 for memory-level parallelism
    for (; r + 3 < end; r += 4) {
        int s0 = g_col[r], s1 = g_col[r + 1], s2 = g_col[r + 2], s3 = g_col[r + 3];
        if (VPL == 4) {
            float4 v0 = ((const float4*)(G + (size_t)s0 * D))[lane];
            float4 v1 = ((const float4*)(G + (size_t)s1 * D))[lane];
            float4 v2 = ((const float4*)(G + (size_t)s2 * D))[lane];
            float4 v3 = ((const float4*)(G + (size_t)s3 * D))[lane];
            acc[0] += v0.x + v1.x + v2.x + v3.x;
            acc[1] += v0.y + v1.y + v2.y + v3.y;
            acc[2] += v0.z + v1.z + v2.z + v3.z;
            acc[3] += v0.w + v1.w + v2.w + v3.w;
        } else {
            float2 v0 = ((const float2*)(G + (size_t)s0 * D))[lane];
            float2 v1 = ((const float2*)(G + (size_t)s1 * D))[lane];
            float2 v2 = ((const float2*)(G + (size_t)s2 * D))[lane];
            float2 v3 = ((const float2*)(G + (size_t)s3 * D))[lane];
            acc[0] += v0.x + v1.x + v2.x + v3.x;
            acc[1] += v0.y + v1.y + v2.y + v3.y;
        }
    }
    for (; r < end; r++) {
        int s = g_col[r];
        if (VPL == 4) {
            float4 v = ((const float4*)(G + (size_t)s * D))[lane];
            acc[0] += v.x; acc[1] += v.y; acc[2] += v.z; acc[3] += v.w;
        } else {
            float2 v = ((const float2*)(G + (size_t)s * D))[lane];
            acc[0] += v.x; acc[1] += v.y;
        }
    }

    const float dv = g_dinv[warp];

    if (!LAYER2) {
        // SELU
        const float alpha = 1.6732632423543772f;
        const float scale = 1.0507009873554805f;
        float o[VPL];
#pragma unroll
        for (int v = 0; v < VPL; v++) {
            float x = dv * acc[v] + bias[lane * VPL + v];
            o[v] = scale * (x > 0.f ? x : alpha * (expf(x) - 1.f));
        }
        if (VPL == 4) {
            float4 w = make_float4(o[0], o[1], o[2], o[3]);
            ((float4*)(out + (size_t)warp * D))[lane] = w;
        }
    } else {
        // log_softmax over D=64 row held by the warp (2 vals/lane)
        float v0 = dv * acc[0] + bias[lane * 2];
        float v1 = dv * acc[1] + bias[lane * 2 + 1];
        float m = fmaxf(v0, v1);
#pragma unroll
        for (int o = 16; o >= 1; o >>= 1) m = fmaxf(m, __shfl_xor_sync(0xffffffffu, m, o));
        float s = expf(v0 - m) + expf(v1 - m);
#pragma unroll
        for (int o = 16; o >= 1; o >>= 1) s += __shfl_xor_sync(0xffffffffu, s, o);
        float l = logf(s);
        float2 w = make_float2(v0 - m - l, v1 - m - l);
        ((float2*)(out + (size_t)warp * D))[lane] = w;
    }
}

// ----------------- launch -----------------
extern "C" void kernel_launch(void* const* d_in, const int* in_sizes, int n_in,
                              void* d_out, int out_size) {
    const float* x  = (const float*)d_in[0];
    const int*   ei = (const int*)d_in[1];
    const float* W1 = (const float*)d_in[2];
    const float* b1 = (const float*)d_in[3];
    const float* W2 = (const float*)d_in[4];
    const float* b2 = (const float*)d_in[5];
    float* out = (float*)d_out;

    const int n = in_sizes[0] / KDIM;     // 100000
    const int e = in_sizes[1] / 2;        // 1600000
    const int* src = ei;
    const int* dst = ei + e;

    // scratch pointers
    float *pA, *pB;
    cudaGetSymbolAddress((void**)&pA, g_bufA);
    cudaGetSymbolAddress((void**)&pB, g_bufB);

    const int nb = (n + 511) / 512;

    // degree + CSR
    k_zero_cnt<<<(n + 255) / 256, 256>>>(n);
    k_count<<<(e + 255) / 256, 256>>>(dst, e);
    k_dinv<<<(n + 255) / 256, 256>>>(n);
    k_scan1<<<nb, 512>>>(n);
    k_scan2<<<1, 1>>>(nb, n);
    k_scan3<<<nb, 512>>>(n);
    k_fill<<<(e + 255) / 256, 256>>>(src, dst, e);

    // layer 1
    const int smem1 = (KDIM * 128 + 64 * 129) * sizeof(float);   // 98560 B
    const int smem2 = (KDIM * 64 + 64 * 129) * sizeof(float);    // 65792 B
    cudaFuncSetAttribute(k_gemm_scale<128>, cudaFuncAttributeMaxDynamicSharedMemorySize, smem1);
    cudaFuncSetAttribute(k_gemm_scale<64>,  cudaFuncAttributeMaxDynamicSharedMemorySize, smem2);

    const int gemm_grid = (n + 63) / 64;
    const int agg_grid = (n * 32 + 255) / 256;

    k_gemm_scale<128><<<gemm_grid, 256, smem1>>>(x, W1, pA, n);
    k_agg<128, false><<<agg_grid, 256>>>(pA, b1, pB, n);

    // layer 2
    k_gemm_scale<64><<<gemm_grid, 256, smem2>>>(pB, W2, pA, n);
    k_agg<64, true><<<agg_grid, 256>>>(pA, b2, out, n);
}

// round 5
// speedup vs baseline: 1.1322x; 1.1322x over previous
#include <cuda_runtime.h>
#include <cuda_bf16.h>
#include <math.h>
#include <cstdint>

// Problem constants: N=100000, E=1600000, D_IN=128, D_H=128, D_OUT=64
#define NN 100000
#define EE 1600000
#define KDIM 128

// -------- device-global scratch (allocations are forbidden) --------
__device__ float g_bufA[(size_t)NN * 128];   // GEMM output G
__device__ float g_bufB[(size_t)NN * 128];   // post-aggregation activations (layer1)
__device__ int   g_cnt[NN];
__device__ int   g_rowptr[NN + 1];
__device__ int   g_wp[NN];
__device__ int   g_col[EE];
__device__ float g_dinv[NN];
__device__ int   g_bsum[512];
__device__ int   g_boff[512];
// bf16 hi/lo weights, [N][K] row-major (K contiguous)  == W^T
__device__ __nv_bfloat16 g_W1hi[128 * 128];
__device__ __nv_bfloat16 g_W1lo[128 * 128];
__device__ __nv_bfloat16 g_W2hi[64 * 128];
__device__ __nv_bfloat16 g_W2lo[64 * 128];

// ================= small helpers =================
__device__ __forceinline__ uint32_t smem_u32(const void* p) {
    uint32_t a;
    asm("{ .reg .u64 t; cvta.to.shared.u64 t, %1; cvt.u32.u64 %0, t; }" : "=r"(a) : "l"(p));
    return a;
}
__device__ __forceinline__ void ldmatrix_x4(uint32_t& r0, uint32_t& r1, uint32_t& r2,
                                            uint32_t& r3, uint32_t addr) {
    asm volatile("ldmatrix.sync.aligned.m8n8.x4.shared.b16 {%0,%1,%2,%3}, [%4];"
                 : "=r"(r0), "=r"(r1), "=r"(r2), "=r"(r3) : "r"(addr));
}
__device__ __forceinline__ void ldmatrix_x2(uint32_t& r0, uint32_t& r1, uint32_t addr) {
    asm volatile("ldmatrix.sync.aligned.m8n8.x2.shared.b16 {%0,%1}, [%2];"
                 : "=r"(r0), "=r"(r1) : "r"(addr));
}
__device__ __forceinline__ void mma_bf16(float* d, const uint32_t* a, const uint32_t* b) {
    asm volatile(
        "mma.sync.aligned.m16n8k16.row.col.f32.bf16.bf16.f32 "
        "{%0,%1,%2,%3}, {%4,%5,%6,%7}, {%8,%9}, {%0,%1,%2,%3};"
        : "+f"(d[0]), "+f"(d[1]), "+f"(d[2]), "+f"(d[3])
        : "r"(a[0]), "r"(a[1]), "r"(a[2]), "r"(a[3]), "r"(b[0]), "r"(b[1]));
}

// ================= CSR build =================
__global__ void k_zero_cnt(int n) {
    int i = blockIdx.x * blockDim.x + threadIdx.x;
    if (i < n) g_cnt[i] = 0;
}
__global__ void k_count(const int* __restrict__ dst, int e) {
    int i = blockIdx.x * blockDim.x + threadIdx.x;
    if (i < e) atomicAdd(&g_cnt[dst[i]], 1);
}
__global__ void k_scan1(int n) {
    __shared__ int sh[512];
    int tid = threadIdx.x;
    int i = blockIdx.x * 512 + tid;
    int v = (i < n) ? g_cnt[i] : 0;
    if (i < n) g_dinv[i] = rsqrtf((float)v + 1.0f);   // self-loop folded in
    sh[tid] = v;
    __syncthreads();
#pragma unroll
    for (int off = 1; off < 512; off <<= 1) {
        int t = (tid >= off) ? sh[tid - off] : 0;
        __syncthreads();
        sh[tid] += t;
        __syncthreads();
    }
    int incl = sh[tid];
    if (i < n) g_rowptr[i] = incl - v;
    if (tid == 511) g_bsum[blockIdx.x] = incl;
}
__global__ void k_scan2(int nb, int n) {
    int run = 0;
    for (int b = 0; b < nb; b++) { g_boff[b] = run; run += g_bsum[b]; }
    g_rowptr[n] = run;
}
__global__ void k_scan3(int n) {
    int i = blockIdx.x * 512 + threadIdx.x;
    if (i < n) {
        int v = g_rowptr[i] + g_boff[blockIdx.x];
        g_rowptr[i] = v;
        g_wp[i] = v;
    }
}
__global__ void k_fill(const int* __restrict__ src, const int* __restrict__ dst, int e) {
    int i = blockIdx.x * blockDim.x + threadIdx.x;
    if (i < e) {
        int d = dst[i];
        int pos = atomicAdd(&g_wp[d], 1);
        g_col[pos] = src[i];
    }
}

// ======== weight convert: fp32 [K][N] -> hi/lo bf16 [N][K] (W^T, K contiguous) ========
__global__ void k_convW(const float* __restrict__ W, __nv_bfloat16* __restrict__ Bhi,
                        __nv_bfloat16* __restrict__ Blo, int NC) {
    int i = blockIdx.x * blockDim.x + threadIdx.x;  // over K*NC
    if (i >= 128 * NC) return;
    int k = i / NC, nn = i % NC;
    float v = W[i];
    __nv_bfloat16 h = __float2bfloat16(v);
    __nv_bfloat16 l = __float2bfloat16(v - __bfloat162float(h));
    Bhi[nn * 128 + k] = h;
    Blo[nn * 128 + k] = l;
}

// ================= mma.sync GEMM: G[r,:] = dinv[r] * (X[r,:128] @ W[:, :NCOL]) =================
// 3-term bf16 compensated: Ahi*Bhi + Ahi*Blo + Alo*Bhi, fp32 accumulate.
// CTA: 256 threads (8 warps), tile 128 x NCOL. Warp w: rows [w*16, w*16+16).
template <int NCOL>
__global__ void __launch_bounds__(256, 1)
k_gemm_mma(const float* __restrict__ X, const __nv_bfloat16* __restrict__ Bhi,
           const __nv_bfloat16* __restrict__ Blo, float* __restrict__ G, int n) {
    constexpr int K = 128;
    constexpr int PAD = 136;                 // halves per row (8 halves pad)
    constexpr int NT = NCOL / 8;             // n-tiles per warp
    constexpr int ABYTES = 128 * PAD * 2;    // 34816 per half
    constexpr int BBYTES = NCOL * PAD * 2;

    extern __shared__ char smem[];
    __nv_bfloat16* sAhi = (__nv_bfloat16*)(smem);
    __nv_bfloat16* sAlo = (__nv_bfloat16*)(smem + ABYTES);
    __nv_bfloat16* sBhi = (__nv_bfloat16*)(smem + 2 * ABYTES);
    __nv_bfloat16* sBlo = (__nv_bfloat16*)(smem + 2 * ABYTES + BBYTES);

    const int tid = threadIdx.x;
    const int wid = tid >> 5;
    const int lane = tid & 31;
    const int rowBase = blockIdx.x * 128;

    // ---- stage B (hi/lo) into padded smem, 16B chunks ----
    {
        const uint4* bh = (const uint4*)Bhi;
        const uint4* bl = (const uint4*)Blo;
        for (int c = tid; c < NCOL * 16; c += 256) {
            int r = c >> 4, c8 = c & 15;        // 8 halves per chunk
            uint4 vh = bh[c], vl = bl[c];
            *(uint4*)(&sBhi[r * PAD + c8 * 8]) = vh;
            *(uint4*)(&sBlo[r * PAD + c8 * 8]) = vl;
        }
    }

    // ---- stage A tile: 128 rows x 128 fp32 -> hi/lo bf16 ----
    for (int i = tid; i < 128 * 32; i += 256) {
        int r = i >> 5, c4 = i & 31;            // float4 index in row
        float4 v = make_float4(0.f, 0.f, 0.f, 0.f);
        int gr = rowBase + r;
        if (gr < n) v = ((const float4*)X)[(size_t)gr * 32 + c4];
        __nv_bfloat16 h0 = __float2bfloat16(v.x), h1 = __float2bfloat16(v.y);
        __nv_bfloat16 h2 = __float2bfloat16(v.z), h3 = __float2bfloat16(v.w);
        __nv_bfloat16 l0 = __float2bfloat16(v.x - __bfloat162float(h0));
        __nv_bfloat16 l1 = __float2bfloat16(v.y - __bfloat162float(h1));
        __nv_bfloat16 l2 = __float2bfloat16(v.z - __bfloat162float(h2));
        __nv_bfloat16 l3 = __float2bfloat16(v.w - __bfloat162float(h3));
        __nv_bfloat162* ph = (__nv_bfloat162*)&sAhi[r * PAD + c4 * 4];
        __nv_bfloat162* pl = (__nv_bfloat162*)&sAlo[r * PAD + c4 * 4];
        ph[0] = __nv_bfloat162(h0, h1); ph[1] = __nv_bfloat162(h2, h3);
        pl[0] = __nv_bfloat162(l0, l1); pl[1] = __nv_bfloat162(l2, l3);
    }
    __syncthreads();

    // ---- per-warp mma mainloop ----
    const int m0 = wid * 16;
    // A ldmatrix lane address: row = m0 + (lane & 15), k-offset = (lane>>4)*8
    const uint32_t aRow = m0 + (lane & 15);
    const uint32_t aK = (lane >> 4) * 8;
    const uint32_t aHiAddr = smem_u32(&sAhi[aRow * PAD + aK]);
    const uint32_t aLoAddr = smem_u32(&sAlo[aRow * PAD + aK]);
    // B ldmatrix lane address: n-row = (lane & 7), k-offset = ((lane>>3)&1)*8
    const uint32_t bRow = (lane & 7);
    const uint32_t bK = ((lane >> 3) & 1) * 8;
    const uint32_t bHiAddr = smem_u32(&sBhi[bRow * PAD + bK]);
    const uint32_t bLoAddr = smem_u32(&sBlo[bRow * PAD + bK]);

    float d[NT][4];
#pragma unroll
    for (int j = 0; j < NT; j++) { d[j][0] = 0.f; d[j][1] = 0.f; d[j][2] = 0.f; d[j][3] = 0.f; }

#pragma unroll
    for (int k0 = 0; k0 < K; k0 += 16) {
        uint32_t ahi[4], alo[4];
        ldmatrix_x4(ahi[0], ahi[1], ahi[2], ahi[3], aHiAddr + k0 * 2);
        ldmatrix_x4(alo[0], alo[1], alo[2], alo[3], aLoAddr + k0 * 2);
#pragma unroll
        for (int j = 0; j < NT; j++) {
            uint32_t bhi[2], blo[2];
            const uint32_t boff = (j * 8) * (PAD * 2) + k0 * 2;
            ldmatrix_x2(bhi[0], bhi[1], bHiAddr + boff);
            ldmatrix_x2(blo[0], blo[1], bLoAddr + boff);
            mma_bf16(d[j], ahi, bhi);
            mma_bf16(d[j], ahi, blo);
            mma_bf16(d[j], alo, bhi);
        }
    }

    // ---- epilogue: dinv row scale + store ----
    const int r0 = rowBase + m0 + (lane >> 2);
    const int r1 = r0 + 8;
    const int cbase = (lane & 3) * 2;
    const float s0 = (r0 < n) ? g_dinv[r0] : 0.f;
    const float s1 = (r1 < n) ? g_dinv[r1] : 0.f;
#pragma unroll
    for (int j = 0; j < NT; j++) {
        int col = j * 8 + cbase;
        if (r0 < n)
            *(float2*)(G + (size_t)r0 * NCOL + col) = make_float2(s0 * d[j][0], s0 * d[j][1]);
        if (r1 < n)
            *(float2*)(G + (size_t)r1 * NCOL + col) = make_float2(s1 * d[j][2], s1 * d[j][3]);
    }
}

// ================= aggregation: one warp per destination node =================
template <int D, bool LAYER2>
__global__ void k_agg(const float* __restrict__ G, const float* __restrict__ bias,
                      float* __restrict__ out, int n) {
    const int warp = (blockIdx.x * blockDim.x + threadIdx.x) >> 5;
    const int lane = threadIdx.x & 31;
    if (warp >= n) return;
    constexpr int VPL = D / 32;

    float acc[VPL];
    {
        const float* row = G + (size_t)warp * D;
        if (VPL == 4) {
            float4 v = ((const float4*)row)[lane];
            acc[0] = v.x; acc[1] = v.y; acc[2] = v.z; acc[3] = v.w;
        } else {
            float2 v = ((const float2*)row)[lane];
            acc[0] = v.x; acc[1] = v.y;
        }
    }

    int r = g_rowptr[warp];
    const int end = g_rowptr[warp + 1];

    for (; r + 3 < end; r += 4) {
        int s0 = g_col[r], s1 = g_col[r + 1], s2 = g_col[r + 2], s3 = g_col[r + 3];
        if (VPL == 4) {
            float4 v0 = ((const float4*)(G + (size_t)s0 * D))[lane];
            float4 v1 = ((const float4*)(G + (size_t)s1 * D))[lane];
            float4 v2 = ((const float4*)(G + (size_t)s2 * D))[lane];
            float4 v3 = ((const float4*)(G + (size_t)s3 * D))[lane];
            acc[0] += v0.x + v1.x + v2.x + v3.x;
            acc[1] += v0.y + v1.y + v2.y + v3.y;
            acc[2] += v0.z + v1.z + v2.z + v3.z;
            acc[3] += v0.w + v1.w + v2.w + v3.w;
        } else {
            float2 v0 = ((const float2*)(G + (size_t)s0 * D))[lane];
            float2 v1 = ((const float2*)(G + (size_t)s1 * D))[lane];
            float2 v2 = ((const float2*)(G + (size_t)s2 * D))[lane];
            float2 v3 = ((const float2*)(G + (size_t)s3 * D))[lane];
            acc[0] += v0.x + v1.x + v2.x + v3.x;
            acc[1] += v0.y + v1.y + v2.y + v3.y;
        }
    }
    for (; r < end; r++) {
        int s = g_col[r];
        if (VPL == 4) {
            float4 v = ((const float4*)(G + (size_t)s * D))[lane];
            acc[0] += v.x; acc[1] += v.y; acc[2] += v.z; acc[3] += v.w;
        } else {
            float2 v = ((const float2*)(G + (size_t)s * D))[lane];
            acc[0] += v.x; acc[1] += v.y;
        }
    }

    const float dv = g_dinv[warp];

    if (!LAYER2) {
        const float alpha = 1.6732632423543772f;
        const float scale = 1.0507009873554805f;
        float o[VPL];
#pragma unroll
        for (int v = 0; v < VPL; v++) {
            float x = dv * acc[v] + bias[lane * VPL + v];
            o[v] = scale * (x > 0.f ? x : alpha * (expf(x) - 1.f));
        }
        if (VPL == 4) {
            ((float4*)(out + (size_t)warp * D))[lane] = make_float4(o[0], o[1], o[2], o[3]);
        }
    } else {
        float v0 = dv * acc[0] + bias[lane * 2];
        float v1 = dv * acc[1] + bias[lane * 2 + 1];
        float m = fmaxf(v0, v1);
#pragma unroll
        for (int o = 16; o >= 1; o >>= 1) m = fmaxf(m, __shfl_xor_sync(0xffffffffu, m, o));
        float s = expf(v0 - m) + expf(v1 - m);
#pragma unroll
        for (int o = 16; o >= 1; o >>= 1) s += __shfl_xor_sync(0xffffffffu, s, o);
        float l = logf(s);
        ((float2*)(out + (size_t)warp * D))[lane] = make_float2(v0 - m - l, v1 - m - l);
    }
}

// ================= launch =================
extern "C" void kernel_launch(void* const* d_in, const int* in_sizes, int n_in,
                              void* d_out, int out_size) {
    const float* x  = (const float*)d_in[0];
    const int*   ei = (const int*)d_in[1];
    const float* W1 = (const float*)d_in[2];
    const float* b1 = (const float*)d_in[3];
    const float* W2 = (const float*)d_in[4];
    const float* b2 = (const float*)d_in[5];
    float* out = (float*)d_out;

    const int n = in_sizes[0] / KDIM;   // 100000
    const int e = in_sizes[1] / 2;      // 1600000
    const int* src = ei;
    const int* dst = ei + e;

    float *pA, *pB;
    __nv_bfloat16 *w1h, *w1l, *w2h, *w2l;
    cudaGetSymbolAddress((void**)&pA, g_bufA);
    cudaGetSymbolAddress((void**)&pB, g_bufB);
    cudaGetSymbolAddress((void**)&w1h, g_W1hi);
    cudaGetSymbolAddress((void**)&w1l, g_W1lo);
    cudaGetSymbolAddress((void**)&w2h, g_W2hi);
    cudaGetSymbolAddress((void**)&w2l, g_W2lo);

    const int nb = (n + 511) / 512;

    // CSR + dinv
    k_zero_cnt<<<(n + 255) / 256, 256>>>(n);
    k_count<<<(e + 255) / 256, 256>>>(dst, e);
    k_scan1<<<nb, 512>>>(n);
    k_scan2<<<1, 1>>>(nb, n);
    k_scan3<<<nb, 512>>>(n);
    k_fill<<<(e + 255) / 256, 256>>>(src, dst, e);

    // weight operand images
    k_convW<<<(128 * 128 + 255) / 256, 256>>>(W1, w1h, w1l, 128);
    k_convW<<<(128 * 64 + 255) / 256, 256>>>(W2, w2h, w2l, 64);

    // GEMMs (mma.sync bf16, 3-term compensated)
    constexpr int SM1 = 2 * (128 * 136 * 2) + 2 * (128 * 136 * 2);  // 139264
    constexpr int SM2 = 2 * (128 * 136 * 2) + 2 * (64 * 136 * 2);   // 104448
    cudaFuncSetAttribute(k_gemm_mma<128>, cudaFuncAttributeMaxDynamicSharedMemorySize, SM1);
    cudaFuncSetAttribute(k_gemm_mma<64>,  cudaFuncAttributeMaxDynamicSharedMemorySize, SM2);

    const int gemm_grid = (n + 127) / 128;   // 782
    const int agg_grid = (n * 32 + 255) / 256;

    k_gemm_mma<128><<<gemm_grid, 256, SM1>>>(x, w1h, w1l, pA, n);
    k_agg<128, false><<<agg_grid, 256>>>(pA, b1, pB, n);
    k_gemm_mma<64><<<gemm_grid, 256, SM2>>>(pB, w2h, w2l, pA, n);
    k_agg<64, true><<<agg_grid, 256>>>(pA, b2, out, n);
}